// round 1
// baseline (speedup 1.0000x reference)
#include <cuda_runtime.h>

// SQEmbedding fused kernel for GB300 (sm_103a).
// B=8, T=4096, D=64, M=1024, N=32768.
// Inputs (metadata order): x(B,D,T) f32, embedding(M,D) f32, log_var_q f32[1],
//                          gumbels(N,M) f32, temperature f32[1].
// Output: quantized (B,D,T) f32, then loss, then perplexity (N*D + 2 floats).

#define BB 8
#define TT 4096
#define DD 64
#define MM 1024
#define NN (BB * TT)
#define ROWS 32
#define NTILES (NN / ROWS)      // 1024
#define THREADS 256
#define CHUNK 128
#define NCH (MM / CHUNK)        // 8
#define XS 65                    // padded x stride (conflict-free column reads)
#define QS 66                    // padded q stride

#define SMEM_FLOATS (ROWS * XS + ROWS * MM + DD * CHUNK + 2 * ROWS * QS + 3 * ROWS + 8)
#define SMEM_BYTES (SMEM_FLOATS * 4)

__device__ float g_e2[MM];        // ||e_m||^2
__device__ int   g_hist[MM];      // hard-assignment histogram
__device__ float g_partial[NTILES]; // per-CTA (recon + neg_entropy) partial sums

// ---------------------------------------------------------------------------
// Prep: zero histogram, precompute codebook squared norms.
// ---------------------------------------------------------------------------
__global__ void prep_kernel(const float* __restrict__ emb) {
    int m = blockIdx.x * blockDim.x + threadIdx.x;
    if (m < MM) {
        g_hist[m] = 0;
        const float4* p = (const float4*)(emb + m * DD);
        float s = 0.f;
#pragma unroll
        for (int i = 0; i < DD / 4; ++i) {
            float4 v = p[i];
            s += v.x * v.x + v.y * v.y + v.z * v.z + v.w * v.w;
        }
        g_e2[m] = s;
    }
}

// ---------------------------------------------------------------------------
// Main fused kernel: one CTA per 32 consecutive frames (same batch b).
// Phases:
//  P0: load x tile (transposed) into smem, compute per-row ||x||^2
//  P1: GEMM1  logits[32][1024] = prec*(x.e) - 0.5*prec*(|x|^2+|e|^2)  (smem)
//  P2: per row: streaming two softmax stats + entropy + argmax; overwrite
//      logits with w = (logit + gumbel)/temperature  (gumbels read ONCE)
//  P3: overwrite w with encodings = exp(w - (cmax + log s1))
//  P4: GEMM2  q[32][64] = encodings @ embedding (split-M halves per warp pair)
//  P5: write quantized (coalesced), accumulate recon + entropy into g_partial
// ---------------------------------------------------------------------------
__global__ __launch_bounds__(THREADS, 1)
void sqembed_main(const float* __restrict__ x,
                  const float* __restrict__ emb,
                  const float* __restrict__ lvq,
                  const float* __restrict__ gum,
                  const float* __restrict__ temp,
                  float* __restrict__ out) {
    extern __shared__ float smem[];
    float* s_x   = smem;                         // ROWS*XS
    float* s_lg  = s_x + ROWS * XS;              // ROWS*MM   (logits -> w -> enc)
    float* s_eb  = s_lg + ROWS * MM;             // DD*CHUNK  (emb chunk, 2 layouts)
    float* s_q   = s_eb + DD * CHUNK;            // 2*ROWS*QS (two m-half partials)
    float* s_x2  = s_q + 2 * ROWS * QS;          // ROWS
    float* s_z1  = s_x2 + ROWS;                  // ROWS (log-norm of gumbel softmax)
    float* s_ent = s_z1 + ROWS;                  // ROWS (sum p*logp per row)
    float* s_red = s_ent + ROWS;                 // 8

    const int tid  = threadIdx.x;
    const int lane = tid & 31;
    const int warp = tid >> 5;
    const int n0   = blockIdx.x * ROWS;
    const int b    = n0 / TT;
    const int t0   = n0 % TT;

    const float prec = __expf(-lvq[0]);
    const float hp   = 0.5f * prec;
    const float invT = 1.0f / temp[0];

    // ---- P0: load x tile, coalesced along t ----
    for (int i = tid; i < ROWS * DD; i += THREADS) {
        int r = i & (ROWS - 1);
        int d = i >> 5;
        s_x[r * XS + d] = x[(b * DD + d) * TT + t0 + r];
    }
    __syncthreads();
    if (tid < ROWS) {
        float s = 0.f;
#pragma unroll
        for (int d = 0; d < DD; ++d) { float v = s_x[tid * XS + d]; s += v * v; }
        s_x2[tid] = s;
    }

    // ---- P1: GEMM1 into smem logits ----
    const int r0 = warp * 4;  // 4 rows per warp
    for (int ch = 0; ch < NCH; ++ch) {
        const int m0 = ch * CHUNK;
        __syncthreads();  // protects s_eb reuse and (first iter) s_x2
        // load chunk transposed with +4d skew (conflict-free float4 reads)
        for (int i = tid; i < CHUNK * DD; i += THREADS) {
            int d  = i & (DD - 1);
            int mi = i >> 6;
            float v = emb[(m0 + mi) * DD + d];
            int col = (mi + 4 * d) & (CHUNK - 1);
            s_eb[d * CHUNK + col] = v;
        }
        __syncthreads();

        float acc[4][4] = {};
#pragma unroll 4
        for (int d = 0; d < DD; ++d) {
            float xv[4];
#pragma unroll
            for (int j = 0; j < 4; ++j) xv[j] = s_x[(r0 + j) * XS + d];
            int col = (4 * lane + 4 * d) & (CHUNK - 1);
            float4 e = *(const float4*)&s_eb[d * CHUNK + col];
#pragma unroll
            for (int j = 0; j < 4; ++j) {
                acc[j][0] += xv[j] * e.x;
                acc[j][1] += xv[j] * e.y;
                acc[j][2] += xv[j] * e.z;
                acc[j][3] += xv[j] * e.w;
            }
        }
        float4 e2 = *(const float4*)&g_e2[m0 + lane * 4];
#pragma unroll
        for (int j = 0; j < 4; ++j) {
            float xx = s_x2[r0 + j];
            float4 lv;
            lv.x = prec * acc[j][0] - hp * (xx + e2.x);
            lv.y = prec * acc[j][1] - hp * (xx + e2.y);
            lv.z = prec * acc[j][2] - hp * (xx + e2.z);
            lv.w = prec * acc[j][3] - hp * (xx + e2.w);
            *(float4*)&s_lg[(r0 + j) * MM + m0 + lane * 4] = lv;
        }
    }
    __syncthreads();

    // ---- P2: streaming softmax stats, entropy, argmax; overwrite with w ----
    for (int j = 0; j < 4; ++j) {
        const int r = r0 + j;
        const float* grow = gum + (size_t)(n0 + r) * MM;
        float* lrow = s_lg + r * MM;

        // k = 0 initializes the online state (avoids -inf arithmetic)
        int m = lane;
        float l = lrow[m];
        float g = __ldg(&grow[m]);
        float w = (l + g) * invT;
        lrow[m] = w;
        float cl = l, s2 = 1.0f, Q = 0.0f;   // plain softmax: max, sum e^(l-cl), sum e^(l-cl)*(l-cl)
        float cw = w, s1 = 1.0f;             // gumbel softmax: max, sum
        int bi = m;                           // argmax index (== argmin distance)

        for (int k = 1; k < MM / 32; ++k) {
            m = lane + 32 * k;
            l = lrow[m];
            g = __ldg(&grow[m]);
            w = (l + g) * invT;
            lrow[m] = w;
            if (l > cl) {
                float f = __expf(cl - l);
                Q  = f * (Q + (cl - l) * s2);
                s2 = s2 * f + 1.0f;
                cl = l;
                bi = m;                       // new strict max -> new argmax
            } else {
                float t = __expf(l - cl);
                s2 += t;
                Q  += t * (l - cl);
            }
            if (w > cw) { s1 = s1 * __expf(cw - w) + 1.0f; cw = w; }
            else        { s1 += __expf(w - cw); }
        }
        // warp reduction of both online states + argmax (first-index tiebreak)
#pragma unroll
        for (int off = 16; off; off >>= 1) {
            float cl2 = __shfl_xor_sync(~0u, cl, off);
            float S2  = __shfl_xor_sync(~0u, s2, off);
            float Q2  = __shfl_xor_sync(~0u, Q,  off);
            int   bi2 = __shfl_xor_sync(~0u, bi, off);
            float cm = fmaxf(cl, cl2);
            float fa = __expf(cl - cm), fb = __expf(cl2 - cm);
            Q  = fa * (Q + (cl - cm) * s2) + fb * (Q2 + (cl2 - cm) * S2);
            s2 = fa * s2 + fb * S2;
            if (cl2 > cl || (cl2 == cl && bi2 < bi)) bi = bi2;
            cl = cm;

            float cw2 = __shfl_xor_sync(~0u, cw, off);
            float S1  = __shfl_xor_sync(~0u, s1, off);
            float cwm = fmaxf(cw, cw2);
            s1 = s1 * __expf(cw - cwm) + S1 * __expf(cw2 - cwm);
            cw = cwm;
        }
        if (lane == 0) {
            s_z1[r]  = cw + __logf(s1);          // enc = exp(w - z1)
            s_ent[r] = Q / s2 - __logf(s2);      // sum_m p*logp (negative)
            atomicAdd(&g_hist[bi], 1);
        }
    }
    __syncthreads();

    // ---- P3: w -> encodings in place ----
    for (int i = tid; i < ROWS * MM; i += THREADS) {
        int r = i >> 10;
        s_lg[i] = __expf(s_lg[i] - s_z1[r]);
    }
    __syncthreads();

    // ---- P4: GEMM2 (quantized = enc @ emb), warps 0-3 / 4-7 split M halves ----
    float qa[8][2] = {};
    const int half = warp >> 2;        // 0 or 1: which half of each chunk's codes
    const int rg   = (warp & 3) * 8;   // 8 rows per warp
    for (int ch = 0; ch < NCH; ++ch) {
        const int m0 = ch * CHUNK;
        __syncthreads();
        // natural layout chunk [mi][d]
        for (int i = tid; i < CHUNK * DD; i += THREADS) {
            int d  = i & (DD - 1);
            int mi = i >> 6;
            s_eb[mi * DD + d] = emb[(m0 + mi) * DD + d];
        }
        __syncthreads();
        const int mb = half * (CHUNK / 2);
#pragma unroll 2
        for (int mi = 0; mi < CHUNK / 2; ++mi) {
            int mm = mb + mi;
            float2 e = *(const float2*)&s_eb[mm * DD + lane * 2];
#pragma unroll
            for (int j = 0; j < 8; ++j) {
                float p = s_lg[(rg + j) * MM + m0 + mm];  // warp-broadcast
                qa[j][0] += p * e.x;
                qa[j][1] += p * e.y;
            }
        }
    }
#pragma unroll
    for (int j = 0; j < 8; ++j) {
        *(float2*)&s_q[(half * ROWS + rg + j) * QS + lane * 2] =
            make_float2(qa[j][0], qa[j][1]);
    }
    __syncthreads();

    // ---- P5: combine halves, write output, recon + entropy into g_partial ----
    float myloss = 0.f;
    for (int i = tid; i < ROWS * DD; i += THREADS) {
        int r = i & 31;
        int d = i >> 5;
        float q = s_q[r * QS + d] + s_q[(ROWS + r) * QS + d];
        out[(b * DD + d) * TT + t0 + r] = q;     // coalesced along r (== t)
        float dx = s_x[r * XS + d] - q;
        myloss += dx * dx;
    }
    myloss *= hp;
    if (tid < ROWS) myloss += s_ent[tid];
#pragma unroll
    for (int off = 16; off; off >>= 1)
        myloss += __shfl_xor_sync(~0u, myloss, off);
    if (lane == 0) s_red[warp] = myloss;
    __syncthreads();
    if (tid == 0) {
        float t = 0.f;
#pragma unroll
        for (int wv = 0; wv < THREADS / 32; ++wv) t += s_red[wv];
        g_partial[blockIdx.x] = t;   // deterministic: one slot per CTA
    }
}

// ---------------------------------------------------------------------------
// Final: loss = mean_b(recon+negent); perplexity from histogram.
// ---------------------------------------------------------------------------
__global__ void final_kernel(float* __restrict__ out, int out_size) {
    __shared__ float sl[32], sp[32];
    int tid = threadIdx.x;  // 1024 threads == NTILES == MM
    float v = g_partial[tid];
    float a = (float)g_hist[tid] * (1.0f / (float)NN);
    float pe = a * __logf(a + 1e-10f);
#pragma unroll
    for (int off = 16; off; off >>= 1) {
        v  += __shfl_xor_sync(~0u, v,  off);
        pe += __shfl_xor_sync(~0u, pe, off);
    }
    if ((tid & 31) == 0) { sl[tid >> 5] = v; sp[tid >> 5] = pe; }
    __syncthreads();
    if (tid == 0) {
        float lv = 0.f, pv = 0.f;
#pragma unroll
        for (int i = 0; i < 32; ++i) { lv += sl[i]; pv += sp[i]; }
        if (out_size >= NN * DD + 2) {
            out[NN * DD]     = lv / (float)BB;   // loss
            out[NN * DD + 1] = __expf(-pv);      // perplexity
        }
    }
}

// ---------------------------------------------------------------------------
extern "C" void kernel_launch(void* const* d_in, const int* in_sizes, int n_in,
                              void* d_out, int out_size) {
    (void)in_sizes; (void)n_in;
    const float* x    = (const float*)d_in[0];
    const float* emb  = (const float*)d_in[1];
    const float* lvq  = (const float*)d_in[2];
    const float* gum  = (const float*)d_in[3];
    const float* temp = (const float*)d_in[4];
    float* out = (float*)d_out;

    cudaFuncSetAttribute(sqembed_main,
                         cudaFuncAttributeMaxDynamicSharedMemorySize, SMEM_BYTES);

    prep_kernel<<<(MM + 255) / 256, 256>>>(emb);
    sqembed_main<<<NTILES, THREADS, SMEM_BYTES>>>(x, emb, lvq, gum, temp, out);
    final_kernel<<<1, 1024>>>(out, out_size);
}

// round 3
// speedup vs baseline: 2.6641x; 2.6641x over previous
#include <cuda_runtime.h>

// SQEmbedding fused kernel for GB300 (sm_103a).  B=8,T=4096,D=64,M=1024,N=32768.
// Inputs: x(B,D,T) f32, embedding(M,D) f32, log_var_q f32[1], gumbels(N,M) f32,
//         temperature f32[1].  Output: quantized(B,D,T) + loss + perplexity.

#define BB 8
#define TT 4096
#define DD 64
#define MM 1024
#define NN (BB * TT)
#define ROWS 32
#define NTILES (NN / ROWS)      // 1024
#define THREADS 512
#define NWARP (THREADS / 32)    // 16
#define CHUNK 128
#define NCH (MM / CHUNK)        // 8
#define XS 68                    // x row stride (16B-aligned rows for float4)
#define ES 65                    // e row stride (conflict-free scalar r/w)
#define QS 66

#define SMEM_FLOATS (ROWS*XS + ROWS*MM + 2*CHUNK*ES + 2*ROWS*QS + 3*ROWS + NWARP)
#define SMEM_BYTES (SMEM_FLOATS * 4)

__device__ float g_e2[MM];          // ||e_m||^2
__device__ int   g_hist[MM];        // hard-assignment histogram
__device__ float g_partial[NTILES]; // per-CTA loss partials (deterministic)

// ---------------------------------------------------------------------------
__global__ void prep_kernel(const float* __restrict__ emb) {
    int m = blockIdx.x * 8 + (threadIdx.x >> 5);
    int lane = threadIdx.x & 31;
    if (m < MM) {
        float2 v = ((const float2*)(emb + m * DD))[lane];
        float s = fmaf(v.x, v.x, v.y * v.y);
#pragma unroll
        for (int off = 16; off; off >>= 1) s += __shfl_xor_sync(~0u, s, off);
        if (lane == 0) { g_e2[m] = s; g_hist[m] = 0; }
    }
}

// ---------------------------------------------------------------------------
__global__ __launch_bounds__(THREADS, 1)
void sqembed_main(const float* __restrict__ x,
                  const float* __restrict__ emb,
                  const float* __restrict__ lvq,
                  const float* __restrict__ gum,
                  const float* __restrict__ temp,
                  float* __restrict__ out) {
    extern __shared__ float smem[];
    float* s_x   = smem;                       // ROWS*XS
    float* s_lg  = s_x + ROWS * XS;            // ROWS*MM  (logits -> w -> ew)
    float* s_eb  = s_lg + ROWS * MM;           // 2 * CHUNK*ES (double buffer)
    float* s_q   = s_eb + 2 * CHUNK * ES;      // 2*ROWS*QS (m-half partials)
    float* s_x2  = s_q + 2 * ROWS * QS;        // ROWS
    float* s_ent = s_x2 + ROWS;                // ROWS
    float* s_inv = s_ent + ROWS;               // ROWS (1/s1 per row)
    float* s_red = s_inv + ROWS;               // NWARP

    const int tid = threadIdx.x, lane = tid & 31, warp = tid >> 5;
    const int n0 = blockIdx.x * ROWS;
    const int b = n0 / TT, t0 = n0 % TT;
    const float prec = __expf(-lvq[0]);
    const float hp = 0.5f * prec;
    const float invT = 1.0f / temp[0];

    // ---- P0: x tile (coalesced along t) + e-chunk0 register prefetch ----
#pragma unroll
    for (int i = tid; i < ROWS * DD; i += THREADS) {
        int r = i & 31, d = i >> 5;
        s_x[r * XS + d] = x[(b * DD + d) * TT + t0 + r];
    }
    float pf[16];
#pragma unroll
    for (int k = 0; k < 16; ++k) pf[k] = emb[tid + THREADS * k];
    __syncthreads();
    {   // per-row ||x||^2 (16 threads per row, float4)
        int r = tid >> 4, c = tid & 15;
        float4 v = *(const float4*)&s_x[r * XS + c * 4];
        float s = fmaf(v.x, v.x, fmaf(v.y, v.y, fmaf(v.z, v.z, v.w * v.w)));
#pragma unroll
        for (int off = 8; off; off >>= 1) s += __shfl_down_sync(~0u, s, off, 16);
        if (c == 0) s_x2[r] = s;
    }

    // ---- GEMM1: logits = prec*(x.e) - hp*(|x|^2+|e|^2)   (lane <-> m) ----
    const int rg1 = (warp & 3) * 8;     // 8 rows
    const int mg1 = (warp >> 2) * 32;   // 32 m per warp (lane-mapped)
    for (int ch = 0; ch < NCH; ++ch) {
        float* eb = s_eb + (ch & 1) * (CHUNK * ES);
#pragma unroll
        for (int k = 0; k < 16; ++k) {
            int idx = tid + THREADS * k;
            eb[(idx >> 6) * ES + (idx & 63)] = pf[k];   // conflict-free STS
        }
        if (ch + 1 < NCH) {
            const float* src = emb + (ch + 1) * (CHUNK * DD);
#pragma unroll
            for (int k = 0; k < 16; ++k) pf[k] = src[tid + THREADS * k];
        }
        __syncthreads();
        float acc[8] = {0, 0, 0, 0, 0, 0, 0, 0};
        const float* erow = eb + (mg1 + lane) * ES;
#pragma unroll
        for (int dw = 0; dw < 16; ++dw) {
            float e0 = erow[dw * 4 + 0], e1 = erow[dw * 4 + 1];
            float e2v = erow[dw * 4 + 2], e3 = erow[dw * 4 + 3];
#pragma unroll
            for (int r = 0; r < 8; ++r) {
                float4 xv = *(const float4*)&s_x[(rg1 + r) * XS + dw * 4];
                acc[r] = fmaf(xv.w, e3, fmaf(xv.z, e2v,
                          fmaf(xv.y, e1, fmaf(xv.x, e0, acc[r]))));
            }
        }
        int m = ch * CHUNK + mg1 + lane;
        float en = g_e2[m];
#pragma unroll
        for (int r = 0; r < 8; ++r)
            s_lg[(rg1 + r) * MM + m] = prec * acc[r] - hp * (s_x2[rg1 + r] + en);
    }
    // prefetch GEMM2 chunk 0 now; softmax hides the global latency
#pragma unroll
    for (int k = 0; k < 16; ++k) pf[k] = emb[tid + THREADS * k];
    __syncthreads();

    // ---- Softmax: warp owns rows 2w, 2w+1; all exps independent ----
#pragma unroll 1
    for (int rr = 0; rr < 2; ++rr) {
        const int r = warp * 2 + rr;
        float* lrow = s_lg + r * MM;
        // pass A: row max (pure fmax chains)
        float4 v0 = *(const float4*)&lrow[lane * 4];
        float ma = v0.x, mb = v0.y, mc = v0.z, md = v0.w;
#pragma unroll
        for (int k = 1; k < 8; ++k) {
            float4 v = *(const float4*)&lrow[lane * 4 + 128 * k];
            ma = fmaxf(ma, v.x); mb = fmaxf(mb, v.y);
            mc = fmaxf(mc, v.z); md = fmaxf(md, v.w);
        }
        float cl = fmaxf(fmaxf(ma, mb), fmaxf(mc, md));
#pragma unroll
        for (int off = 16; off; off >>= 1)
            cl = fmaxf(cl, __shfl_xor_sync(~0u, cl, off));
        // pass B: stats + argmax + w-write (single gumbels read)
        const float* grow = gum + (size_t)(n0 + r) * MM;
        float sa = 0, sb = 0, sc = 0, sd = 0;
        float Qa = 0, Qb = 0, Qc = 0, Qd = 0;
        float ca = -1e30f, cb = -1e30f, cc = -1e30f, cd = -1e30f;
        int bi = 0x7FFFFFFF;
#pragma unroll
        for (int k = 0; k < 8; ++k) {
            int m = lane * 4 + 128 * k;
            float4 l4 = *(const float4*)&lrow[m];
            float4 g4 = *(const float4*)&grow[m];
            float dxa = l4.x - cl, dxb = l4.y - cl, dxc = l4.z - cl, dxd = l4.w - cl;
            float ea = __expf(dxa), eb2 = __expf(dxb);
            float ec = __expf(dxc), ed = __expf(dxd);
            sa += ea; sb += eb2; sc += ec; sd += ed;
            Qa = fmaf(ea, dxa, Qa); Qb = fmaf(eb2, dxb, Qb);
            Qc = fmaf(ec, dxc, Qc); Qd = fmaf(ed, dxd, Qd);
            if (l4.x == cl) bi = min(bi, m);
            if (l4.y == cl) bi = min(bi, m + 1);
            if (l4.z == cl) bi = min(bi, m + 2);
            if (l4.w == cl) bi = min(bi, m + 3);
            float4 w4;
            w4.x = (l4.x + g4.x) * invT; w4.y = (l4.y + g4.y) * invT;
            w4.z = (l4.z + g4.z) * invT; w4.w = (l4.w + g4.w) * invT;
            ca = fmaxf(ca, w4.x); cb = fmaxf(cb, w4.y);
            cc = fmaxf(cc, w4.z); cd = fmaxf(cd, w4.w);
            *(float4*)&lrow[m] = w4;
        }
        float s2 = (sa + sb) + (sc + sd);
        float Q = (Qa + Qb) + (Qc + Qd);
        float cw = fmaxf(fmaxf(ca, cb), fmaxf(cc, cd));
#pragma unroll
        for (int off = 16; off; off >>= 1) {
            s2 += __shfl_xor_sync(~0u, s2, off);
            Q  += __shfl_xor_sync(~0u, Q, off);
            cw  = fmaxf(cw, __shfl_xor_sync(~0u, cw, off));
            bi  = min(bi, __shfl_xor_sync(~0u, bi, off));
        }
        if (lane == 0) {
            s_ent[r] = Q / s2 - __logf(s2);   // sum_m p*log p
            atomicAdd(&g_hist[bi], 1);
        }
        // pass C: ew = exp(w - cw); 1/s1 folded into GEMM2 epilogue
        float s1a = 0, s1b = 0, s1c = 0, s1d = 0;
#pragma unroll
        for (int k = 0; k < 8; ++k) {
            int m = lane * 4 + 128 * k;
            float4 w4 = *(const float4*)&lrow[m];
            w4.x = __expf(w4.x - cw); w4.y = __expf(w4.y - cw);
            w4.z = __expf(w4.z - cw); w4.w = __expf(w4.w - cw);
            s1a += w4.x; s1b += w4.y; s1c += w4.z; s1d += w4.w;
            *(float4*)&lrow[m] = w4;
        }
        float s1 = (s1a + s1b) + (s1c + s1d);
#pragma unroll
        for (int off = 16; off; off >>= 1) s1 += __shfl_xor_sync(~0u, s1, off);
        if (lane == 0) s_inv[r] = 1.0f / s1;
    }

    // ---- GEMM2: q = (ew @ e) * (1/s1)   (lane <-> d, m-halves split) ----
    const int rg2 = (warp & 3) * 8;
    const int dh = (warp >> 2) & 1;
    const int mh = warp >> 3;
    const int dcol = dh * 32 + lane;
    float qa[8] = {0, 0, 0, 0, 0, 0, 0, 0};
    for (int ch = 0; ch < NCH; ++ch) {
        float* eb = s_eb + (ch & 1) * (CHUNK * ES);
#pragma unroll
        for (int k = 0; k < 16; ++k) {
            int idx = tid + THREADS * k;
            eb[(idx >> 6) * ES + (idx & 63)] = pf[k];
        }
        if (ch + 1 < NCH) {
            const float* src = emb + (ch + 1) * (CHUNK * DD);
#pragma unroll
            for (int k = 0; k < 16; ++k) pf[k] = src[tid + THREADS * k];
        }
        __syncthreads();
#pragma unroll
        for (int mw = 0; mw < 16; ++mw) {
            int ml = mh * 64 + mw * 4;
            float e0 = eb[(ml + 0) * ES + dcol];
            float e1 = eb[(ml + 1) * ES + dcol];
            float e2v = eb[(ml + 2) * ES + dcol];
            float e3 = eb[(ml + 3) * ES + dcol];
#pragma unroll
            for (int r = 0; r < 8; ++r) {
                float4 p = *(const float4*)&s_lg[(rg2 + r) * MM + ch * CHUNK + ml];
                qa[r] = fmaf(p.w, e3, fmaf(p.z, e2v,
                          fmaf(p.y, e1, fmaf(p.x, e0, qa[r]))));
            }
        }
    }
#pragma unroll
    for (int r = 0; r < 8; ++r)
        s_q[(mh * ROWS + rg2 + r) * QS + dcol] = qa[r];
    __syncthreads();

    // ---- P5: combine halves, scale by 1/s1, write out, loss ----
    float myloss = 0.f;
#pragma unroll
    for (int i = tid; i < ROWS * DD; i += THREADS) {
        int r = i & 31, d = i >> 5;
        float q = (s_q[r * QS + d] + s_q[(ROWS + r) * QS + d]) * s_inv[r];
        out[(b * DD + d) * TT + t0 + r] = q;       // coalesced along r (== t)
        float dx = s_x[r * XS + d] - q;
        myloss = fmaf(dx, dx, myloss);
    }
    myloss *= hp;
    if (tid < ROWS) myloss += s_ent[tid];
#pragma unroll
    for (int off = 16; off; off >>= 1)
        myloss += __shfl_xor_sync(~0u, myloss, off);
    if (lane == 0) s_red[warp] = myloss;
    __syncthreads();
    if (tid == 0) {
        float t = 0.f;
#pragma unroll
        for (int w2 = 0; w2 < NWARP; ++w2) t += s_red[w2];
        g_partial[blockIdx.x] = t;
    }
}

// ---------------------------------------------------------------------------
__global__ void final_kernel(float* __restrict__ out, int out_size) {
    __shared__ float sl[32], sp[32];
    int tid = threadIdx.x;  // 1024 == NTILES == MM
    float v = g_partial[tid];
    float a = (float)g_hist[tid] * (1.0f / (float)NN);
    float pe = a * __logf(a + 1e-10f);
#pragma unroll
    for (int off = 16; off; off >>= 1) {
        v  += __shfl_xor_sync(~0u, v, off);
        pe += __shfl_xor_sync(~0u, pe, off);
    }
    if ((tid & 31) == 0) { sl[tid >> 5] = v; sp[tid >> 5] = pe; }
    __syncthreads();
    if (tid == 0) {
        float lv = 0.f, pv = 0.f;
#pragma unroll
        for (int i = 0; i < 32; ++i) { lv += sl[i]; pv += sp[i]; }
        if (out_size >= NN * DD + 2) {
            out[NN * DD]     = lv / (float)BB;
            out[NN * DD + 1] = __expf(-pv);
        }
    }
}

// ---------------------------------------------------------------------------
extern "C" void kernel_launch(void* const* d_in, const int* in_sizes, int n_in,
                              void* d_out, int out_size) {
    (void)in_sizes; (void)n_in;
    const float* x    = (const float*)d_in[0];
    const float* emb  = (const float*)d_in[1];
    const float* lvq  = (const float*)d_in[2];
    const float* gum  = (const float*)d_in[3];
    const float* temp = (const float*)d_in[4];
    float* out = (float*)d_out;

    cudaFuncSetAttribute(sqembed_main,
                         cudaFuncAttributeMaxDynamicSharedMemorySize, SMEM_BYTES);

    prep_kernel<<<MM / 8, 256>>>(emb);
    sqembed_main<<<NTILES, THREADS, SMEM_BYTES>>>(x, emb, lvq, gum, temp, out);
    final_kernel<<<1, 1024>>>(out, out_size);
}

// round 4
// speedup vs baseline: 2.6702x; 1.0023x over previous
#include <cuda_runtime.h>

// SQEmbedding fused kernel for GB300 (sm_103a).  B=8,T=4096,D=64,M=1024,N=32768.
// Inputs: x(B,D,T) f32, embedding(M,D) f32, log_var_q f32[1], gumbels(N,M) f32,
//         temperature f32[1].  Output: quantized(B,D,T) + loss + perplexity.

#define BB 8
#define TT 4096
#define DD 64
#define MM 1024
#define NN (BB * TT)
#define ROWS 32
#define NTILES (NN / ROWS)      // 1024
#define THREADS 512
#define NWARP (THREADS / 32)    // 16
#define CHUNK 128
#define NCH (MM / CHUNK)        // 8
#define XS 68                    // x row stride (16B-aligned rows for float4)
#define ES 65                    // e row stride (conflict-free scalar r/w)
#define QS 66

#define SMEM_FLOATS (ROWS*XS + ROWS*MM + 2*CHUNK*ES + 2*ROWS*QS + 3*ROWS + NWARP)
#define SMEM_BYTES (SMEM_FLOATS * 4)

__device__ float g_e2[MM];          // ||e_m||^2
__device__ int   g_hist[MM];        // hard-assignment histogram
__device__ float g_partial[NTILES]; // per-CTA loss partials (deterministic)

// ---------------------------------------------------------------------------
__global__ void prep_kernel(const float* __restrict__ emb) {
    int m = blockIdx.x * 8 + (threadIdx.x >> 5);
    int lane = threadIdx.x & 31;
    if (m < MM) {
        float2 v = ((const float2*)(emb + m * DD))[lane];
        float s = fmaf(v.x, v.x, v.y * v.y);
#pragma unroll
        for (int off = 16; off; off >>= 1) s += __shfl_xor_sync(~0u, s, off);
        if (lane == 0) { g_e2[m] = s; g_hist[m] = 0; }
    }
}

// ---------------------------------------------------------------------------
__global__ __launch_bounds__(THREADS, 1)
void sqembed_main(const float* __restrict__ x,
                  const float* __restrict__ emb,
                  const float* __restrict__ lvq,
                  const float* __restrict__ gum,
                  const float* __restrict__ temp,
                  float* __restrict__ out) {
    extern __shared__ float smem[];
    float* s_x   = smem;                       // ROWS*XS
    float* s_lg  = s_x + ROWS * XS;            // ROWS*MM  (logits -> w -> ew)
    float* s_eb  = s_lg + ROWS * MM;           // 2 * CHUNK*ES (double buffer)
    float* s_q   = s_eb + 2 * CHUNK * ES;      // 2*ROWS*QS (m-half partials)
    float* s_x2  = s_q + 2 * ROWS * QS;        // ROWS
    float* s_ent = s_x2 + ROWS;                // ROWS
    float* s_inv = s_ent + ROWS;               // ROWS (1/s1 per row)
    float* s_red = s_inv + ROWS;               // NWARP

    const int tid = threadIdx.x, lane = tid & 31, warp = tid >> 5;
    const int n0 = blockIdx.x * ROWS;
    const int b = n0 / TT, t0 = n0 % TT;
    const float prec = __expf(-lvq[0]);
    const float hp = 0.5f * prec;
    const float invT = 1.0f / temp[0];

    // ---- P0: x tile (coalesced along t) + e-chunk0 register prefetch ----
#pragma unroll
    for (int i = tid; i < ROWS * DD; i += THREADS) {
        int r = i & 31, d = i >> 5;
        s_x[r * XS + d] = x[(b * DD + d) * TT + t0 + r];
    }
    float pf[16];
#pragma unroll
    for (int k = 0; k < 16; ++k) pf[k] = emb[tid + THREADS * k];
    __syncthreads();
    {   // per-row ||x||^2 (16 threads per row, float4)
        int r = tid >> 4, c = tid & 15;
        float4 v = *(const float4*)&s_x[r * XS + c * 4];
        float s = fmaf(v.x, v.x, fmaf(v.y, v.y, fmaf(v.z, v.z, v.w * v.w)));
#pragma unroll
        for (int off = 8; off; off >>= 1) s += __shfl_down_sync(~0u, s, off, 16);
        if (c == 0) s_x2[r] = s;
    }

    // ---- GEMM1: logits = prec*(x.e) - hp*(|x|^2+|e|^2)   (lane <-> m) ----
    const int rg1 = (warp & 3) * 8;     // 8 rows
    const int mg1 = (warp >> 2) * 32;   // 32 m per warp (lane-mapped)
    for (int ch = 0; ch < NCH; ++ch) {
        float* eb = s_eb + (ch & 1) * (CHUNK * ES);
#pragma unroll
        for (int k = 0; k < 16; ++k) {
            int idx = tid + THREADS * k;
            eb[(idx >> 6) * ES + (idx & 63)] = pf[k];   // conflict-free STS
        }
        if (ch + 1 < NCH) {
            const float* src = emb + (ch + 1) * (CHUNK * DD);
#pragma unroll
            for (int k = 0; k < 16; ++k) pf[k] = src[tid + THREADS * k];
        }
        __syncthreads();
        float acc[8] = {0, 0, 0, 0, 0, 0, 0, 0};
        const float* erow = eb + (mg1 + lane) * ES;
#pragma unroll
        for (int dw = 0; dw < 16; ++dw) {
            float e0 = erow[dw * 4 + 0], e1 = erow[dw * 4 + 1];
            float e2v = erow[dw * 4 + 2], e3 = erow[dw * 4 + 3];
#pragma unroll
            for (int r = 0; r < 8; ++r) {
                float4 xv = *(const float4*)&s_x[(rg1 + r) * XS + dw * 4];
                acc[r] = fmaf(xv.w, e3, fmaf(xv.z, e2v,
                          fmaf(xv.y, e1, fmaf(xv.x, e0, acc[r]))));
            }
        }
        int m = ch * CHUNK + mg1 + lane;
        float en = g_e2[m];
#pragma unroll
        for (int r = 0; r < 8; ++r)
            s_lg[(rg1 + r) * MM + m] = prec * acc[r] - hp * (s_x2[rg1 + r] + en);
    }
    // prefetch GEMM2 chunk 0 now; softmax hides the global latency
#pragma unroll
    for (int k = 0; k < 16; ++k) pf[k] = emb[tid + THREADS * k];
    __syncthreads();

    // ---- Softmax: warp owns rows 2w, 2w+1; all exps independent ----
#pragma unroll 1
    for (int rr = 0; rr < 2; ++rr) {
        const int r = warp * 2 + rr;
        float* lrow = s_lg + r * MM;
        // pass A: row max (pure fmax chains)
        float4 v0 = *(const float4*)&lrow[lane * 4];
        float ma = v0.x, mb = v0.y, mc = v0.z, md = v0.w;
#pragma unroll
        for (int k = 1; k < 8; ++k) {
            float4 v = *(const float4*)&lrow[lane * 4 + 128 * k];
            ma = fmaxf(ma, v.x); mb = fmaxf(mb, v.y);
            mc = fmaxf(mc, v.z); md = fmaxf(md, v.w);
        }
        float cl = fmaxf(fmaxf(ma, mb), fmaxf(mc, md));
#pragma unroll
        for (int off = 16; off; off >>= 1)
            cl = fmaxf(cl, __shfl_xor_sync(~0u, cl, off));
        // pass B: stats + argmax + w-write (single gumbels read)
        const float* grow = gum + (size_t)(n0 + r) * MM;
        float sa = 0, sb = 0, sc = 0, sd = 0;
        float Qa = 0, Qb = 0, Qc = 0, Qd = 0;
        float ca = -1e30f, cb = -1e30f, cc = -1e30f, cd = -1e30f;
        int bi = 0x7FFFFFFF;
#pragma unroll
        for (int k = 0; k < 8; ++k) {
            int m = lane * 4 + 128 * k;
            float4 l4 = *(const float4*)&lrow[m];
            float4 g4 = *(const float4*)&grow[m];
            float dxa = l4.x - cl, dxb = l4.y - cl, dxc = l4.z - cl, dxd = l4.w - cl;
            float ea = __expf(dxa), eb2 = __expf(dxb);
            float ec = __expf(dxc), ed = __expf(dxd);
            sa += ea; sb += eb2; sc += ec; sd += ed;
            Qa = fmaf(ea, dxa, Qa); Qb = fmaf(eb2, dxb, Qb);
            Qc = fmaf(ec, dxc, Qc); Qd = fmaf(ed, dxd, Qd);
            if (l4.x == cl) bi = min(bi, m);
            if (l4.y == cl) bi = min(bi, m + 1);
            if (l4.z == cl) bi = min(bi, m + 2);
            if (l4.w == cl) bi = min(bi, m + 3);
            float4 w4;
            w4.x = (l4.x + g4.x) * invT; w4.y = (l4.y + g4.y) * invT;
            w4.z = (l4.z + g4.z) * invT; w4.w = (l4.w + g4.w) * invT;
            ca = fmaxf(ca, w4.x); cb = fmaxf(cb, w4.y);
            cc = fmaxf(cc, w4.z); cd = fmaxf(cd, w4.w);
            *(float4*)&lrow[m] = w4;
        }
        float s2 = (sa + sb) + (sc + sd);
        float Q = (Qa + Qb) + (Qc + Qd);
        float cw = fmaxf(fmaxf(ca, cb), fmaxf(cc, cd));
#pragma unroll
        for (int off = 16; off; off >>= 1) {
            s2 += __shfl_xor_sync(~0u, s2, off);
            Q  += __shfl_xor_sync(~0u, Q, off);
            cw  = fmaxf(cw, __shfl_xor_sync(~0u, cw, off));
            bi  = min(bi, __shfl_xor_sync(~0u, bi, off));
        }
        if (lane == 0) {
            s_ent[r] = Q / s2 - __logf(s2);   // sum_m p*log p
            atomicAdd(&g_hist[bi], 1);
        }
        // pass C: ew = exp(w - cw); 1/s1 folded into GEMM2 epilogue
        float s1a = 0, s1b = 0, s1c = 0, s1d = 0;
#pragma unroll
        for (int k = 0; k < 8; ++k) {
            int m = lane * 4 + 128 * k;
            float4 w4 = *(const float4*)&lrow[m];
            w4.x = __expf(w4.x - cw); w4.y = __expf(w4.y - cw);
            w4.z = __expf(w4.z - cw); w4.w = __expf(w4.w - cw);
            s1a += w4.x; s1b += w4.y; s1c += w4.z; s1d += w4.w;
            *(float4*)&lrow[m] = w4;
        }
        float s1 = (s1a + s1b) + (s1c + s1d);
#pragma unroll
        for (int off = 16; off; off >>= 1) s1 += __shfl_xor_sync(~0u, s1, off);
        if (lane == 0) s_inv[r] = 1.0f / s1;
    }

    // ---- GEMM2: q = (ew @ e) * (1/s1)   (lane <-> d, m-halves split) ----
    const int rg2 = (warp & 3) * 8;
    const int dh = (warp >> 2) & 1;
    const int mh = warp >> 3;
    const int dcol = dh * 32 + lane;
    float qa[8] = {0, 0, 0, 0, 0, 0, 0, 0};
    for (int ch = 0; ch < NCH; ++ch) {
        float* eb = s_eb + (ch & 1) * (CHUNK * ES);
#pragma unroll
        for (int k = 0; k < 16; ++k) {
            int idx = tid + THREADS * k;
            eb[(idx >> 6) * ES + (idx & 63)] = pf[k];
        }
        if (ch + 1 < NCH) {
            const float* src = emb + (ch + 1) * (CHUNK * DD);
#pragma unroll
            for (int k = 0; k < 16; ++k) pf[k] = src[tid + THREADS * k];
        }
        __syncthreads();
#pragma unroll
        for (int mw = 0; mw < 16; ++mw) {
            int ml = mh * 64 + mw * 4;
            float e0 = eb[(ml + 0) * ES + dcol];
            float e1 = eb[(ml + 1) * ES + dcol];
            float e2v = eb[(ml + 2) * ES + dcol];
            float e3 = eb[(ml + 3) * ES + dcol];
#pragma unroll
            for (int r = 0; r < 8; ++r) {
                float4 p = *(const float4*)&s_lg[(rg2 + r) * MM + ch * CHUNK + ml];
                qa[r] = fmaf(p.w, e3, fmaf(p.z, e2v,
                          fmaf(p.y, e1, fmaf(p.x, e0, qa[r]))));
            }
        }
    }
#pragma unroll
    for (int r = 0; r < 8; ++r)
        s_q[(mh * ROWS + rg2 + r) * QS + dcol] = qa[r];
    __syncthreads();

    // ---- P5: combine halves, scale by 1/s1, write out, loss ----
    float myloss = 0.f;
#pragma unroll
    for (int i = tid; i < ROWS * DD; i += THREADS) {
        int r = i & 31, d = i >> 5;
        float q = (s_q[r * QS + d] + s_q[(ROWS + r) * QS + d]) * s_inv[r];
        out[(b * DD + d) * TT + t0 + r] = q;       // coalesced along r (== t)
        float dx = s_x[r * XS + d] - q;
        myloss = fmaf(dx, dx, myloss);
    }
    myloss *= hp;
    if (tid < ROWS) myloss += s_ent[tid];
#pragma unroll
    for (int off = 16; off; off >>= 1)
        myloss += __shfl_xor_sync(~0u, myloss, off);
    if (lane == 0) s_red[warp] = myloss;
    __syncthreads();
    if (tid == 0) {
        float t = 0.f;
#pragma unroll
        for (int w2 = 0; w2 < NWARP; ++w2) t += s_red[w2];
        g_partial[blockIdx.x] = t;
    }
}

// ---------------------------------------------------------------------------
__global__ void final_kernel(float* __restrict__ out, int out_size) {
    __shared__ float sl[32], sp[32];
    int tid = threadIdx.x;  // 1024 == NTILES == MM
    float v = g_partial[tid];
    float a = (float)g_hist[tid] * (1.0f / (float)NN);
    float pe = a * __logf(a + 1e-10f);
#pragma unroll
    for (int off = 16; off; off >>= 1) {
        v  += __shfl_xor_sync(~0u, v, off);
        pe += __shfl_xor_sync(~0u, pe, off);
    }
    if ((tid & 31) == 0) { sl[tid >> 5] = v; sp[tid >> 5] = pe; }
    __syncthreads();
    if (tid == 0) {
        float lv = 0.f, pv = 0.f;
#pragma unroll
        for (int i = 0; i < 32; ++i) { lv += sl[i]; pv += sp[i]; }
        if (out_size >= NN * DD + 2) {
            out[NN * DD]     = lv / (float)BB;
            out[NN * DD + 1] = __expf(-pv);
        }
    }
}

// ---------------------------------------------------------------------------
extern "C" void kernel_launch(void* const* d_in, const int* in_sizes, int n_in,
                              void* d_out, int out_size) {
    (void)in_sizes; (void)n_in;
    const float* x    = (const float*)d_in[0];
    const float* emb  = (const float*)d_in[1];
    const float* lvq  = (const float*)d_in[2];
    const float* gum  = (const float*)d_in[3];
    const float* temp = (const float*)d_in[4];
    float* out = (float*)d_out;

    cudaFuncSetAttribute(sqembed_main,
                         cudaFuncAttributeMaxDynamicSharedMemorySize, SMEM_BYTES);

    prep_kernel<<<MM / 8, 256>>>(emb);
    sqembed_main<<<NTILES, THREADS, SMEM_BYTES>>>(x, emb, lvq, gum, temp, out);
    final_kernel<<<1, 1024>>>(out, out_size);
}